// round 6
// baseline (speedup 1.0000x reference)
#include <cuda_runtime.h>
#include <math.h>

#define N_CLOUDS 16

// ---------------- static scratch (no allocations allowed) ----------------
__device__ __align__(16) float g_A[(size_t)16384 * 8064];   // reused by all 3 layers
__device__ __align__(16) float g_x1[32768 * 64];
__device__ __align__(16) float g_x2in[16384 * 64];
__device__ __align__(16) float g_x2out[16384 * 64];
__device__ __align__(16) float g_x3in[4096 * 64];
__device__ __align__(16) float g_x3out[4096 * 128];
__device__ __align__(16) float g_pos2[16384 * 3];
__device__ __align__(16) float g_pos3[4096 * 3];
__device__ __align__(16) float g_w1e[128 * 64];
__device__ __align__(16) float g_w2e[8064 * 64];
__device__ __align__(16) float g_w3e[8064 * 128];
__device__ __align__(16) float g_pool[N_CLOUDS * 128];
__device__ __align__(16) float g_cnt[N_CLOUDS];

__device__ __forceinline__ int lowerb(const int* __restrict__ a, int n, int v) {
    int lo = 0, hi = n;
    while (lo < hi) { int m = (lo + hi) >> 1; if (a[m] < v) lo = m + 1; else hi = m; }
    return lo;
}

__device__ __forceinline__ float eluf(float v) { return v > 0.f ? v : expm1f(v); }

// ---------------- W_ext = [W ; R ; zero-pad] ----------------
__global__ void concat_w(const float* __restrict__ W, const float* __restrict__ R,
                         float* __restrict__ dst, int wrows, int rrows, int cout, int totRows)
{
    int i = blockIdx.x * blockDim.x + threadIdx.x;
    int tot = totRows * cout;
    if (i >= tot) return;
    int r = i / cout, c = i - r * cout;
    float v = 0.f;
    if (r < wrows) v = W[r * cout + c];
    else if (r < wrows + rrows) v = R[(r - wrows) * cout + c];
    dst[i] = v;
}

// ---------------- layer 1 A build (Cin=1): A_ext [n,128] ----------------
// Thread t owns kernel-index t (t<125): deterministic, no atomics.
__global__ void build_A1(const float* __restrict__ pos, const int* __restrict__ src,
                         const int* __restrict__ tgt, int nE, float inv2r,
                         float* __restrict__ Aout)
{
    int n = blockIdx.x;
    int tid = threadIdx.x;  // 128
    int s0 = lowerb(tgt, nE, n);
    int s1 = lowerb(tgt, nE, n + 1);
    float tx = pos[n * 3 + 0], ty = pos[n * 3 + 1], tz = pos[n * 3 + 2];
    float acc = 0.f;
    for (int e = s0; e < s1; e++) {
        int sN = src[e];
        float px = fminf(fmaxf((tx - pos[sN * 3 + 0]) * inv2r + 0.5f, 0.f), 1.f) * 4.f;
        float py = fminf(fmaxf((ty - pos[sN * 3 + 1]) * inv2r + 0.5f, 0.f), 1.f) * 4.f;
        float pz = fminf(fmaxf((tz - pos[sN * 3 + 2]) * inv2r + 0.5f, 0.f), 1.f) * 4.f;
        float bx = floorf(px), by = floorf(py), bz = floorf(pz);
        float fx = px - bx, fy = py - by, fz = pz - bz;
        int ix = (int)bx, iy = (int)by, iz = (int)bz;
#pragma unroll
        for (int s = 0; s < 8; s++) {
            int b0 = s & 1, b1 = (s >> 1) & 1, b2 = s >> 2;
            float w = (b0 ? fx : 1.f - fx) * (b1 ? fy : 1.f - fy) * (b2 ? fz : 1.f - fz);
            int wi = min(ix + b0, 4) + 5 * min(iy + b1, 4) + 25 * min(iz + b2, 4);
            if (wi == tid) acc += w;
        }
    }
    float invd = 1.f / fmaxf((float)(s1 - s0), 1.f);
    float out;
    if (tid < 125) out = acc * invd;
    else if (tid == 125) out = 1.f;  // root term: x == 1
    else out = 0.f;                  // K padding to 128
    Aout[(size_t)n * 128 + tid] = out;
}

// ---------------- layers 2/3 A build (Cin=64): A_ext [n,8064] ----------------
// 64 threads, thread = channel c. A[k*64+c] touched only by thread c -> race-free.
__global__ void build_A64(const float* __restrict__ xin, const float* __restrict__ pos,
                          const int* __restrict__ src, const int* __restrict__ tgt, int nE,
                          float inv2r, float* __restrict__ Aout)
{
    __shared__ float A[125 * 64];
    int n = blockIdx.x;
    int c = threadIdx.x;  // 64
    for (int k = 0; k < 125; k++) A[k * 64 + c] = 0.f;
    int s0 = lowerb(tgt, nE, n);
    int s1 = lowerb(tgt, nE, n + 1);
    float tx = pos[n * 3 + 0], ty = pos[n * 3 + 1], tz = pos[n * 3 + 2];
    for (int e = s0; e < s1; e++) {
        int sN = src[e];
        float xj = xin[(size_t)sN * 64 + c];
        float px = fminf(fmaxf((tx - pos[sN * 3 + 0]) * inv2r + 0.5f, 0.f), 1.f) * 4.f;
        float py = fminf(fmaxf((ty - pos[sN * 3 + 1]) * inv2r + 0.5f, 0.f), 1.f) * 4.f;
        float pz = fminf(fmaxf((tz - pos[sN * 3 + 2]) * inv2r + 0.5f, 0.f), 1.f) * 4.f;
        float bx = floorf(px), by = floorf(py), bz = floorf(pz);
        float fx = px - bx, fy = py - by, fz = pz - bz;
        int ix = (int)bx, iy = (int)by, iz = (int)bz;
#pragma unroll
        for (int s = 0; s < 8; s++) {
            int b0 = s & 1, b1 = (s >> 1) & 1, b2 = s >> 2;
            float w = (b0 ? fx : 1.f - fx) * (b1 ? fy : 1.f - fy) * (b2 ? fz : 1.f - fz);
            int wi = min(ix + b0, 4) + 5 * min(iy + b1, 4) + 25 * min(iz + b2, 4);
            A[wi * 64 + c] += w * xj;
        }
    }
    float invd = 1.f / fmaxf((float)(s1 - s0), 1.f);
    size_t base = (size_t)n * 8064;
    for (int k = 0; k < 125; k++) Aout[base + k * 64 + c] = A[k * 64 + c] * invd;
    Aout[base + 8000 + c] = xin[(size_t)n * 64 + c];   // root columns (unscaled)
}

// ---------------- generic row gather ----------------
__global__ void gather_rows(const float* __restrict__ srcv, const int* __restrict__ idx,
                            float* __restrict__ dst, int n, int C)
{
    int i = blockIdx.x * blockDim.x + threadIdx.x;
    if (i >= n * C) return;
    int r = i / C, c = i - r * C;
    dst[i] = srcv[(size_t)idx[r] * C + c];
}

// ---------------- SGEMM (+bias+ELU): C[M,N] = A[M,K]@B[K,N] ----------------
// BM=128, BN=64, BK=16, 128 threads, 8x8 per thread. M%128==0, N%64==0, K%16==0.
__global__ void __launch_bounds__(128)
sgemm_elu(const float* __restrict__ A, const float* __restrict__ B,
          const float* __restrict__ bias, float* __restrict__ C, int N, int Kd)
{
    const int BM = 128, BN = 64, BK = 16;
    __shared__ float As[BK * BM];  // transposed: As[k*BM + m]
    __shared__ float Bs[BK * BN];
    int tid = threadIdx.x;
    size_t rowBase = (size_t)blockIdx.x * BM;
    int colBase = blockIdx.y * BN;

    int aRow = tid >> 2;          // 0..31
    int aCol = (tid & 3) << 2;    // 0,4,8,12
    int bRow = tid >> 4;          // 0..7
    int bCol = (tid & 15) << 2;   // 0..60

    const float* Ag = A + (rowBase + aRow) * (size_t)Kd + aCol;
    const float* Bg = B + (size_t)bRow * N + colBase + bCol;

    int tr = (tid >> 3) << 3;     // 0..120 step 8
    int tc = (tid & 7) << 3;      // 0..56 step 8

    float acc[8][8];
#pragma unroll
    for (int i = 0; i < 8; i++)
#pragma unroll
        for (int j = 0; j < 8; j++) acc[i][j] = 0.f;

    for (int k0 = 0; k0 < Kd; k0 += BK) {
#pragma unroll
        for (int l = 0; l < 4; l++) {
            float4 av = *(const float4*)(Ag + (size_t)k0 + (size_t)(l * 32) * Kd);
            int m = aRow + l * 32;
            As[(aCol + 0) * BM + m] = av.x;
            As[(aCol + 1) * BM + m] = av.y;
            As[(aCol + 2) * BM + m] = av.z;
            As[(aCol + 3) * BM + m] = av.w;
        }
#pragma unroll
        for (int l = 0; l < 2; l++) {
            float4 bv = *(const float4*)(Bg + (size_t)(k0 + l * 8) * N);
            *(float4*)(Bs + (bRow + l * 8) * BN + bCol) = bv;
        }
        __syncthreads();
#pragma unroll
        for (int kk = 0; kk < BK; kk++) {
            float ar[8], br[8];
            *(float4*)(ar)     = *(const float4*)(As + kk * BM + tr);
            *(float4*)(ar + 4) = *(const float4*)(As + kk * BM + tr + 4);
            *(float4*)(br)     = *(const float4*)(Bs + kk * BN + tc);
            *(float4*)(br + 4) = *(const float4*)(Bs + kk * BN + tc + 4);
#pragma unroll
            for (int i = 0; i < 8; i++)
#pragma unroll
                for (int j = 0; j < 8; j++) acc[i][j] += ar[i] * br[j];
        }
        __syncthreads();
    }
#pragma unroll
    for (int i = 0; i < 8; i++) {
        size_t row = rowBase + tr + i;
#pragma unroll
        for (int j = 0; j < 8; j++) {
            float v = acc[i][j] + bias[colBase + tc + j];
            C[row * N + colBase + tc + j] = eluf(v);
        }
    }
}

// ---------------- pooling ----------------
__global__ void zero_pool(float* __restrict__ sums, float* __restrict__ cnt)
{
    int i = blockIdx.x * blockDim.x + threadIdx.x;
    if (i < N_CLOUDS * 128) sums[i] = 0.f;
    if (i < N_CLOUDS) cnt[i] = 0.f;
}

__global__ void pool_kernel(const float* __restrict__ x3, const int* __restrict__ batch,
                            const int* __restrict__ idx1, const int* __restrict__ idx2,
                            int n3, float* __restrict__ sums, float* __restrict__ cnt)
{
    int i = blockIdx.x * blockDim.x + threadIdx.x;
    if (i >= n3 * 128) return;
    int j = i >> 7, c = i & 127;
    int b = batch[idx1[idx2[j]]];
    atomicAdd(&sums[b * 128 + c], x3[i]);
    if (c == 0) atomicAdd(&cnt[b], 1.f);
}

// ---------------- MLP head + log_softmax, one block per cloud ----------------
__global__ void head_kernel(const float* __restrict__ sums, const float* __restrict__ cnt,
                            const float* __restrict__ lw1, const float* __restrict__ lb1,
                            const float* __restrict__ lw2, const float* __restrict__ lb2,
                            const float* __restrict__ lw3, const float* __restrict__ lb3,
                            float* __restrict__ out)
{
    __shared__ float g[128], h1[256], h2[256], lg[10];
    int b = blockIdx.x, tid = threadIdx.x;  // 256 threads
    if (tid < 128) g[tid] = sums[b * 128 + tid] / fmaxf(cnt[b], 1.f);
    __syncthreads();
    float a = lb1[tid];
    for (int c = 0; c < 128; c++) a += g[c] * lw1[c * 256 + tid];
    h1[tid] = eluf(a);
    __syncthreads();
    a = lb2[tid];
    for (int c = 0; c < 256; c++) a += h1[c] * lw2[c * 256 + tid];
    h2[tid] = eluf(a);
    __syncthreads();
    if (tid < 10) {
        a = lb3[tid];
        for (int c = 0; c < 256; c++) a += h2[c] * lw3[c * 10 + tid];
        lg[tid] = a;
    }
    __syncthreads();
    if (tid == 0) {
        float m = lg[0];
        for (int k = 1; k < 10; k++) m = fmaxf(m, lg[k]);
        float s = 0.f;
        for (int k = 0; k < 10; k++) s += expf(lg[k] - m);
        float ls = logf(s);
        for (int k = 0; k < 10; k++) out[b * 10 + k] = lg[k] - m - ls;
    }
}

// ---------------- host driver (graph-capturable: kernel launches only) -------
extern "C" void kernel_launch(void* const* d_in, const int* in_sizes, int n_in,
                              void* d_out, int out_size)
{
    const float* pos = (const float*)d_in[0];
    const int* batch = (const int*)d_in[1];
    const int* src1 = (const int*)d_in[2];
    const int* tgt1 = (const int*)d_in[3];
    const int* src2 = (const int*)d_in[4];
    const int* tgt2 = (const int*)d_in[5];
    const int* src3 = (const int*)d_in[6];
    const int* tgt3 = (const int*)d_in[7];
    const int* idx1 = (const int*)d_in[8];
    const int* idx2 = (const int*)d_in[9];
    const float* W1 = (const float*)d_in[10];
    const float* R1 = (const float*)d_in[11];
    const float* b1 = (const float*)d_in[12];
    const float* W2 = (const float*)d_in[13];
    const float* R2 = (const float*)d_in[14];
    const float* b2 = (const float*)d_in[15];
    const float* W3 = (const float*)d_in[16];
    const float* R3 = (const float*)d_in[17];
    const float* b3 = (const float*)d_in[18];
    const float* lw1 = (const float*)d_in[19];
    const float* lb1 = (const float*)d_in[20];
    const float* lw2 = (const float*)d_in[21];
    const float* lb2 = (const float*)d_in[22];
    const float* lw3 = (const float*)d_in[23];
    const float* lb3 = (const float*)d_in[24];
    float* out = (float*)d_out;

    int n1 = in_sizes[0] / 3;
    int E1 = in_sizes[2], E2 = in_sizes[4], E3 = in_sizes[6];
    int n2 = in_sizes[8], n3 = in_sizes[9];

    float *pA, *px1, *px2in, *px2out, *px3in, *px3out, *ppos2, *ppos3;
    float *pw1, *pw2, *pw3, *ppool, *pcnt;
    cudaGetSymbolAddress((void**)&pA, g_A);
    cudaGetSymbolAddress((void**)&px1, g_x1);
    cudaGetSymbolAddress((void**)&px2in, g_x2in);
    cudaGetSymbolAddress((void**)&px2out, g_x2out);
    cudaGetSymbolAddress((void**)&px3in, g_x3in);
    cudaGetSymbolAddress((void**)&px3out, g_x3out);
    cudaGetSymbolAddress((void**)&ppos2, g_pos2);
    cudaGetSymbolAddress((void**)&ppos3, g_pos3);
    cudaGetSymbolAddress((void**)&pw1, g_w1e);
    cudaGetSymbolAddress((void**)&pw2, g_w2e);
    cudaGetSymbolAddress((void**)&pw3, g_w3e);
    cudaGetSymbolAddress((void**)&ppool, g_pool);
    cudaGetSymbolAddress((void**)&pcnt, g_cnt);

    // weight concat (W_ext = [W ; R ; pad])
    concat_w<<<(128 * 64 + 255) / 256, 256>>>(W1, R1, pw1, 125, 1, 64, 128);
    concat_w<<<(8064 * 64 + 255) / 256, 256>>>(W2, R2, pw2, 8000, 64, 64, 8064);
    concat_w<<<(8064 * 128 + 255) / 256, 256>>>(W3, R3, pw3, 8000, 64, 128, 8064);

    // ---- layer 1 (n1=32768, Cin=1, Cout=64, r=0.2) ----
    build_A1<<<n1, 128>>>(pos, src1, tgt1, E1, 1.f / 0.4f, pA);
    {
        dim3 grid(n1 / 128, 64 / 64);
        sgemm_elu<<<grid, 128>>>(pA, pw1, b1, px1, 64, 128);
    }

    // ---- layer 2 (n2=16384, Cin=64, Cout=64, r=0.4) ----
    gather_rows<<<(n2 * 64 + 255) / 256, 256>>>(px1, idx1, px2in, n2, 64);
    gather_rows<<<(n2 * 3 + 255) / 256, 256>>>(pos, idx1, ppos2, n2, 3);
    build_A64<<<n2, 64>>>(px2in, ppos2, src2, tgt2, E2, 1.f / 0.8f, pA);
    {
        dim3 grid(n2 / 128, 64 / 64);
        sgemm_elu<<<grid, 128>>>(pA, pw2, b2, px2out, 64, 8064);
    }

    // ---- layer 3 (n3=4096, Cin=64, Cout=128, r=1.0) ----
    gather_rows<<<(n3 * 64 + 255) / 256, 256>>>(px2out, idx2, px3in, n3, 64);
    gather_rows<<<(n3 * 3 + 255) / 256, 256>>>(ppos2, idx2, ppos3, n3, 3);
    build_A64<<<n3, 64>>>(px3in, ppos3, src3, tgt3, E3, 1.f / 2.0f, pA);
    {
        dim3 grid(n3 / 128, 128 / 64);
        sgemm_elu<<<grid, 128>>>(pA, pw3, b3, px3out, 128, 8064);
    }

    // ---- pool + head ----
    zero_pool<<<8, 256>>>(ppool, pcnt);
    pool_kernel<<<(n3 * 128 + 255) / 256, 256>>>(px3out, batch, idx1, idx2, n3, ppool, pcnt);
    head_kernel<<<N_CLOUDS, 256>>>(ppool, pcnt, lw1, lb1, lw2, lb2, lw3, lb3, out);
}

// round 7
// speedup vs baseline: 1.6653x; 1.6653x over previous
#include <cuda_runtime.h>
#include <math.h>
#include <stdint.h>

#define N_CLOUDS 16

// ---------------- static scratch (no allocations allowed) ----------------
__device__ __align__(16) float g_A[(size_t)16384 * 8064];   // reused by all 3 layers
__device__ __align__(16) float g_x1[32768 * 64];
__device__ __align__(16) float g_x2in[16384 * 64];
__device__ __align__(16) float g_x2out[16384 * 64];
__device__ __align__(16) float g_x3in[4096 * 64];
__device__ __align__(16) float g_x3out[4096 * 128];
__device__ __align__(16) float g_pos2[16384 * 3];
__device__ __align__(16) float g_pos3[4096 * 3];
__device__ __align__(16) float g_w1e[128 * 64];
__device__ __align__(16) float g_w2e[8064 * 64];
__device__ __align__(16) float g_w3e[8064 * 128];
__device__ __align__(16) float g_pool[N_CLOUDS * 128];
__device__ __align__(16) float g_cnt[N_CLOUDS];

__device__ __forceinline__ int lowerb(const int* __restrict__ a, int n, int v) {
    int lo = 0, hi = n;
    while (lo < hi) { int m = (lo + hi) >> 1; if (a[m] < v) lo = m + 1; else hi = m; }
    return lo;
}

__device__ __forceinline__ float eluf(float v) { return v > 0.f ? v : expm1f(v); }

__device__ __forceinline__ uint32_t f2tf32(float v) {
    uint32_t u;
    asm("cvt.rna.tf32.f32 %0, %1;" : "=r"(u) : "f"(v));
    return u;
}

// ---------------- W_ext = [W ; R ; zero-pad] ----------------
__global__ void concat_w(const float* __restrict__ W, const float* __restrict__ R,
                         float* __restrict__ dst, int wrows, int rrows, int cout, int totRows)
{
    int i = blockIdx.x * blockDim.x + threadIdx.x;
    int tot = totRows * cout;
    if (i >= tot) return;
    int r = i / cout, c = i - r * cout;
    float v = 0.f;
    if (r < wrows) v = W[r * cout + c];
    else if (r < wrows + rrows) v = R[(r - wrows) * cout + c];
    dst[i] = v;
}

// ---------------- layer 1 A build (Cin=1): A_ext [n,128] ----------------
// One warp per node; lanes cover edges; shared atomics (tiny contention).
__global__ void __launch_bounds__(128) build_A1(
    const float* __restrict__ pos, const int* __restrict__ src,
    const int* __restrict__ tgt, int nE, float inv2r, float* __restrict__ Aout)
{
    __shared__ float A[4][128];
    int warp = threadIdx.x >> 5, lane = threadIdx.x & 31;
    int n = blockIdx.x * 4 + warp;
    float* Aw = A[warp];
    Aw[lane] = 0.f; Aw[lane + 32] = 0.f; Aw[lane + 64] = 0.f; Aw[lane + 96] = 0.f;
    __syncwarp();
    int s0 = lowerb(tgt, nE, n);
    int s1 = lowerb(tgt, nE, n + 1);
    float tx = pos[n * 3 + 0], ty = pos[n * 3 + 1], tz = pos[n * 3 + 2];
    for (int e = s0 + lane; e < s1; e += 32) {
        int sN = src[e];
        float px = fminf(fmaxf((tx - pos[sN * 3 + 0]) * inv2r + 0.5f, 0.f), 1.f) * 4.f;
        float py = fminf(fmaxf((ty - pos[sN * 3 + 1]) * inv2r + 0.5f, 0.f), 1.f) * 4.f;
        float pz = fminf(fmaxf((tz - pos[sN * 3 + 2]) * inv2r + 0.5f, 0.f), 1.f) * 4.f;
        float bx = floorf(px), by = floorf(py), bz = floorf(pz);
        float fx = px - bx, fy = py - by, fz = pz - bz;
        int ix = (int)bx, iy = (int)by, iz = (int)bz;
#pragma unroll
        for (int s = 0; s < 8; s++) {
            int b0 = s & 1, b1 = (s >> 1) & 1, b2 = s >> 2;
            float w = (b0 ? fx : 1.f - fx) * (b1 ? fy : 1.f - fy) * (b2 ? fz : 1.f - fz);
            int wi = min(ix + b0, 4) + 5 * min(iy + b1, 4) + 25 * min(iz + b2, 4);
            atomicAdd(&Aw[wi], w);
        }
    }
    __syncwarp();
    float invd = 1.f / fmaxf((float)(s1 - s0), 1.f);
#pragma unroll
    for (int j = 0; j < 4; j++) {
        int idx = lane + j * 32;
        float out;
        if (idx < 125) out = Aw[idx] * invd;
        else if (idx == 125) out = 1.f;   // root term: x == 1
        else out = 0.f;                   // padding
        Aout[(size_t)n * 128 + idx] = out;
    }
}

// ---------------- layers 2/3 A build (Cin=64): A_ext [n,8064] ----------------
// 64 threads (thread = channel). Per-edge (w, wi) staged once edge-parallel,
// then applied channel-parallel -> no redundant spline math, no races.
__global__ void __launch_bounds__(64) build_A64(
    const float* __restrict__ xin, const float* __restrict__ pos,
    const int* __restrict__ src, const int* __restrict__ tgt, int nE,
    float inv2r, float* __restrict__ Aout)
{
    __shared__ float A[8000];          // 125*64
    __shared__ float2 ew[32 * 8];
    __shared__ int esrc[32];
    int n = blockIdx.x;
    int tid = threadIdx.x;  // 64
    float4 z = make_float4(0.f, 0.f, 0.f, 0.f);
    for (int i = tid; i < 2000; i += 64) ((float4*)A)[i] = z;
    int s0 = lowerb(tgt, nE, n);
    int s1 = lowerb(tgt, nE, n + 1);
    float tx = pos[n * 3 + 0], ty = pos[n * 3 + 1], tz = pos[n * 3 + 2];

    for (int e0 = s0; e0 < s1; e0 += 32) {
        int cnt = min(32, s1 - e0);
        __syncthreads();
        if (tid < cnt) {
            int e = e0 + tid;
            int sN = src[e];
            esrc[tid] = sN;
            float px = fminf(fmaxf((tx - pos[sN * 3 + 0]) * inv2r + 0.5f, 0.f), 1.f) * 4.f;
            float py = fminf(fmaxf((ty - pos[sN * 3 + 1]) * inv2r + 0.5f, 0.f), 1.f) * 4.f;
            float pz = fminf(fmaxf((tz - pos[sN * 3 + 2]) * inv2r + 0.5f, 0.f), 1.f) * 4.f;
            float bx = floorf(px), by = floorf(py), bz = floorf(pz);
            float fx = px - bx, fy = py - by, fz = pz - bz;
            int ix = (int)bx, iy = (int)by, iz = (int)bz;
#pragma unroll
            for (int s = 0; s < 8; s++) {
                int b0 = s & 1, b1 = (s >> 1) & 1, b2 = s >> 2;
                float w = (b0 ? fx : 1.f - fx) * (b1 ? fy : 1.f - fy) * (b2 ? fz : 1.f - fz);
                int wi = min(ix + b0, 4) + 5 * min(iy + b1, 4) + 25 * min(iz + b2, 4);
                ew[tid * 8 + s] = make_float2(w, __int_as_float(wi << 6));
            }
        }
        __syncthreads();
        for (int j = 0; j < cnt; j++) {
            float xj = xin[(size_t)esrc[j] * 64 + tid];
#pragma unroll
            for (int s = 0; s < 8; s++) {
                float2 p = ew[j * 8 + s];
                A[__float_as_int(p.y) + tid] += p.x * xj;
            }
        }
    }
    __syncthreads();
    float invd = 1.f / fmaxf((float)(s1 - s0), 1.f);
    size_t base = (size_t)n * 8064;
    for (int i = tid; i < 2000; i += 64) {
        float4 v = ((float4*)A)[i];
        v.x *= invd; v.y *= invd; v.z *= invd; v.w *= invd;
        *(float4*)(Aout + base + i * 4) = v;
    }
    Aout[base + 8000 + tid] = xin[(size_t)n * 64 + tid];   // root columns (unscaled)
}

// ---------------- generic row gather ----------------
__global__ void gather_rows(const float* __restrict__ srcv, const int* __restrict__ idx,
                            float* __restrict__ dst, int n, int C)
{
    int i = blockIdx.x * blockDim.x + threadIdx.x;
    if (i >= n * C) return;
    int r = i / C, c = i - r * C;
    dst[i] = srcv[(size_t)idx[r] * C + c];
}

// ---------------- tf32 tensor-core GEMM (+bias+ELU) ----------------
// C[M,N] = A[M,K]@B[K,N], row-major. Requires M%BM==0, N%64==0, K%32==0.
// 256 threads = 8 warps, warp tile (BM/WARPS_M) x (64/WARPS_N), mma m16n8k8.
template<int BM, int WARPS_M, int WARPS_N>
__global__ void __launch_bounds__(256) mma_gemm_elu(
    const float* __restrict__ A, const float* __restrict__ B,
    const float* __restrict__ bias, float* __restrict__ C, int N, int Kd)
{
    constexpr int BN = 64, BK = 32;
    constexpr int WM = BM / WARPS_M;
    constexpr int WN = BN / WARPS_N;
    constexpr int MT = WM / 16, NT = WN / 8;
    constexpr int ASTR = BK + 4;   // 36: conflict-free frag loads
    constexpr int BSTR = 72;       // (8k + n) % 32 distinct
    __shared__ uint32_t As[BM * ASTR];
    __shared__ uint32_t Bs[BK * BSTR];

    int tid = threadIdx.x, warp = tid >> 5, lane = tid & 31;
    int warp_m = warp % WARPS_M, warp_n = warp / WARPS_M;
    int m0 = warp_m * WM, n0 = warp_n * WN;
    size_t rowBase = (size_t)blockIdx.x * BM;
    int colBase = blockIdx.y * BN;
    const int g = lane >> 2, tg = lane & 3;

    float acc[MT][NT][4] = {};

    for (int k0 = 0; k0 < Kd; k0 += BK) {
        // --- stage A tile (BM x 32) as tf32 ---
#pragma unroll
        for (int i = 0; i < BM / 32; i++) {
            int id = tid + i * 256;          // over [BM][8] float4
            int r = id >> 3, c4 = (id & 7) << 2;
            float4 v = *(const float4*)(A + (rowBase + r) * (size_t)Kd + k0 + c4);
            uint4 u;
            u.x = f2tf32(v.x); u.y = f2tf32(v.y); u.z = f2tf32(v.z); u.w = f2tf32(v.w);
            *(uint4*)(As + r * ASTR + c4) = u;
        }
        // --- stage B tile (32 x 64) as tf32 ---
#pragma unroll
        for (int i = 0; i < 2; i++) {
            int id = tid + i * 256;          // over [32][16] float4
            int r = id >> 4, c4 = (id & 15) << 2;
            float4 v = *(const float4*)(B + (size_t)(k0 + r) * N + colBase + c4);
            uint4 u;
            u.x = f2tf32(v.x); u.y = f2tf32(v.y); u.z = f2tf32(v.z); u.w = f2tf32(v.w);
            *(uint4*)(Bs + r * BSTR + c4) = u;
        }
        __syncthreads();

#pragma unroll
        for (int ks = 0; ks < 4; ks++) {
            int k8 = ks * 8;
            uint32_t af[MT][4], bf[NT][2];
#pragma unroll
            for (int mt = 0; mt < MT; mt++) {
                int r = m0 + mt * 16 + g;
                af[mt][0] = As[r * ASTR + k8 + tg];
                af[mt][1] = As[(r + 8) * ASTR + k8 + tg];
                af[mt][2] = As[r * ASTR + k8 + tg + 4];
                af[mt][3] = As[(r + 8) * ASTR + k8 + tg + 4];
            }
#pragma unroll
            for (int nt = 0; nt < NT; nt++) {
                int c = n0 + nt * 8 + g;
                bf[nt][0] = Bs[(k8 + tg) * BSTR + c];
                bf[nt][1] = Bs[(k8 + tg + 4) * BSTR + c];
            }
#pragma unroll
            for (int mt = 0; mt < MT; mt++)
#pragma unroll
                for (int nt = 0; nt < NT; nt++) {
                    asm volatile(
                        "mma.sync.aligned.m16n8k8.row.col.f32.tf32.tf32.f32 "
                        "{%0,%1,%2,%3}, {%4,%5,%6,%7}, {%8,%9}, {%0,%1,%2,%3};"
                        : "+f"(acc[mt][nt][0]), "+f"(acc[mt][nt][1]),
                          "+f"(acc[mt][nt][2]), "+f"(acc[mt][nt][3])
                        : "r"(af[mt][0]), "r"(af[mt][1]), "r"(af[mt][2]), "r"(af[mt][3]),
                          "r"(bf[nt][0]), "r"(bf[nt][1]));
                }
        }
        __syncthreads();
    }

    // --- epilogue: bias + ELU, coalesced float2 stores ---
#pragma unroll
    for (int mt = 0; mt < MT; mt++) {
        size_t r0 = rowBase + m0 + mt * 16 + g;
#pragma unroll
        for (int nt = 0; nt < NT; nt++) {
            int c = colBase + n0 + nt * 8 + (tg << 1);
            float b0v = bias[c], b1v = bias[c + 1];
            float2 o0 = make_float2(eluf(acc[mt][nt][0] + b0v), eluf(acc[mt][nt][1] + b1v));
            float2 o1 = make_float2(eluf(acc[mt][nt][2] + b0v), eluf(acc[mt][nt][3] + b1v));
            *(float2*)(C + r0 * N + c) = o0;
            *(float2*)(C + (r0 + 8) * N + c) = o1;
        }
    }
}

// ---------------- pooling ----------------
__global__ void zero_pool(float* __restrict__ sums, float* __restrict__ cnt)
{
    int i = blockIdx.x * blockDim.x + threadIdx.x;
    if (i < N_CLOUDS * 128) sums[i] = 0.f;
    if (i < N_CLOUDS) cnt[i] = 0.f;
}

__global__ void pool_kernel(const float* __restrict__ x3, const int* __restrict__ batch,
                            const int* __restrict__ idx1, const int* __restrict__ idx2,
                            int n3, float* __restrict__ sums, float* __restrict__ cnt)
{
    int i = blockIdx.x * blockDim.x + threadIdx.x;
    if (i >= n3 * 128) return;
    int j = i >> 7, c = i & 127;
    int b = batch[idx1[idx2[j]]];
    atomicAdd(&sums[b * 128 + c], x3[i]);
    if (c == 0) atomicAdd(&cnt[b], 1.f);
}

// ---------------- MLP head + log_softmax, one block per cloud ----------------
__global__ void head_kernel(const float* __restrict__ sums, const float* __restrict__ cnt,
                            const float* __restrict__ lw1, const float* __restrict__ lb1,
                            const float* __restrict__ lw2, const float* __restrict__ lb2,
                            const float* __restrict__ lw3, const float* __restrict__ lb3,
                            float* __restrict__ out)
{
    __shared__ float g[128], h1[256], h2[256], lg[10];
    int b = blockIdx.x, tid = threadIdx.x;  // 256 threads
    if (tid < 128) g[tid] = sums[b * 128 + tid] / fmaxf(cnt[b], 1.f);
    __syncthreads();
    float a = lb1[tid];
    for (int c = 0; c < 128; c++) a += g[c] * lw1[c * 256 + tid];
    h1[tid] = eluf(a);
    __syncthreads();
    a = lb2[tid];
    for (int c = 0; c < 256; c++) a += h1[c] * lw2[c * 256 + tid];
    h2[tid] = eluf(a);
    __syncthreads();
    if (tid < 10) {
        a = lb3[tid];
        for (int c = 0; c < 256; c++) a += h2[c] * lw3[c * 10 + tid];
        lg[tid] = a;
    }
    __syncthreads();
    if (tid == 0) {
        float m = lg[0];
        for (int k = 1; k < 10; k++) m = fmaxf(m, lg[k]);
        float s = 0.f;
        for (int k = 0; k < 10; k++) s += expf(lg[k] - m);
        float ls = logf(s);
        for (int k = 0; k < 10; k++) out[b * 10 + k] = lg[k] - m - ls;
    }
}

// ---------------- host driver (graph-capturable: kernel launches only) -------
extern "C" void kernel_launch(void* const* d_in, const int* in_sizes, int n_in,
                              void* d_out, int out_size)
{
    const float* pos = (const float*)d_in[0];
    const int* batch = (const int*)d_in[1];
    const int* src1 = (const int*)d_in[2];
    const int* tgt1 = (const int*)d_in[3];
    const int* src2 = (const int*)d_in[4];
    const int* tgt2 = (const int*)d_in[5];
    const int* src3 = (const int*)d_in[6];
    const int* tgt3 = (const int*)d_in[7];
    const int* idx1 = (const int*)d_in[8];
    const int* idx2 = (const int*)d_in[9];
    const float* W1 = (const float*)d_in[10];
    const float* R1 = (const float*)d_in[11];
    const float* b1 = (const float*)d_in[12];
    const float* W2 = (const float*)d_in[13];
    const float* R2 = (const float*)d_in[14];
    const float* b2 = (const float*)d_in[15];
    const float* W3 = (const float*)d_in[16];
    const float* R3 = (const float*)d_in[17];
    const float* b3 = (const float*)d_in[18];
    const float* lw1 = (const float*)d_in[19];
    const float* lb1 = (const float*)d_in[20];
    const float* lw2 = (const float*)d_in[21];
    const float* lb2 = (const float*)d_in[22];
    const float* lw3 = (const float*)d_in[23];
    const float* lb3 = (const float*)d_in[24];
    float* out = (float*)d_out;

    int n1 = in_sizes[0] / 3;
    int E1 = in_sizes[2], E2 = in_sizes[4], E3 = in_sizes[6];
    int n2 = in_sizes[8], n3 = in_sizes[9];

    float *pA, *px1, *px2in, *px2out, *px3in, *px3out, *ppos2, *ppos3;
    float *pw1, *pw2, *pw3, *ppool, *pcnt;
    cudaGetSymbolAddress((void**)&pA, g_A);
    cudaGetSymbolAddress((void**)&px1, g_x1);
    cudaGetSymbolAddress((void**)&px2in, g_x2in);
    cudaGetSymbolAddress((void**)&px2out, g_x2out);
    cudaGetSymbolAddress((void**)&px3in, g_x3in);
    cudaGetSymbolAddress((void**)&px3out, g_x3out);
    cudaGetSymbolAddress((void**)&ppos2, g_pos2);
    cudaGetSymbolAddress((void**)&ppos3, g_pos3);
    cudaGetSymbolAddress((void**)&pw1, g_w1e);
    cudaGetSymbolAddress((void**)&pw2, g_w2e);
    cudaGetSymbolAddress((void**)&pw3, g_w3e);
    cudaGetSymbolAddress((void**)&ppool, g_pool);
    cudaGetSymbolAddress((void**)&pcnt, g_cnt);

    // weight concat (W_ext = [W ; R ; pad])
    concat_w<<<(128 * 64 + 255) / 256, 256>>>(W1, R1, pw1, 125, 1, 64, 128);
    concat_w<<<(8064 * 64 + 255) / 256, 256>>>(W2, R2, pw2, 8000, 64, 64, 8064);
    concat_w<<<(8064 * 128 + 255) / 256, 256>>>(W3, R3, pw3, 8000, 64, 128, 8064);

    // ---- layer 1 (n1=32768, Cin=1, Cout=64, r=0.2) ----
    build_A1<<<n1 / 4, 128>>>(pos, src1, tgt1, E1, 1.f / 0.4f, pA);
    mma_gemm_elu<128, 4, 2><<<dim3(n1 / 128, 1), 256>>>(pA, pw1, b1, px1, 64, 128);

    // ---- layer 2 (n2=16384, Cin=64, Cout=64, r=0.4) ----
    gather_rows<<<(n2 * 64 + 255) / 256, 256>>>(px1, idx1, px2in, n2, 64);
    gather_rows<<<(n2 * 3 + 255) / 256, 256>>>(pos, idx1, ppos2, n2, 3);
    build_A64<<<n2, 64>>>(px2in, ppos2, src2, tgt2, E2, 1.f / 0.8f, pA);
    mma_gemm_elu<128, 4, 2><<<dim3(n2 / 128, 1), 256>>>(pA, pw2, b2, px2out, 64, 8064);

    // ---- layer 3 (n3=4096, Cin=64, Cout=128, r=1.0) ----
    gather_rows<<<(n3 * 64 + 255) / 256, 256>>>(px2out, idx2, px3in, n3, 64);
    gather_rows<<<(n3 * 3 + 255) / 256, 256>>>(ppos2, idx2, ppos3, n3, 3);
    build_A64<<<n3, 64>>>(px3in, ppos3, src3, tgt3, E3, 1.f / 2.0f, pA);
    mma_gemm_elu<64, 2, 4><<<dim3(n3 / 64, 2), 256>>>(pA, pw3, b3, px3out, 128, 8064);

    // ---- pool + head ----
    zero_pool<<<8, 256>>>(ppool, pcnt);
    pool_kernel<<<(n3 * 128 + 255) / 256, 256>>>(px3out, batch, idx1, idx2, n3, ppool, pcnt);
    head_kernel<<<N_CLOUDS, 256>>>(ppool, pcnt, lw1, lb1, lw2, lb2, lw3, lb3, out);
}

// round 8
// speedup vs baseline: 3.0719x; 1.8447x over previous
#include <cuda_runtime.h>
#include <cuda_bf16.h>
#include <math.h>
#include <stdint.h>

#define N_CLOUDS 16

// ---------------- static scratch (no allocations allowed) ----------------
__device__ __align__(16) __nv_bfloat16 g_A[(size_t)16384 * 8064];  // reused by all layers
__device__ __align__(16) float g_x1[32768 * 64];
__device__ __align__(16) float g_x2in[16384 * 64];
__device__ __align__(16) float g_x2out[16384 * 64];
__device__ __align__(16) float g_x3in[4096 * 64];
__device__ __align__(16) float g_x3out[4096 * 128];
__device__ __align__(16) float g_pos2[16384 * 3];
__device__ __align__(16) float g_pos3[4096 * 3];
__device__ __align__(16) __nv_bfloat16 g_w1e[64 * 128];    // transposed [N][K]
__device__ __align__(16) __nv_bfloat16 g_w2e[64 * 8064];   // transposed [N][K]
__device__ __align__(16) __nv_bfloat16 g_w3e[128 * 8064];  // transposed [N][K]
__device__ __align__(16) float g_pool[N_CLOUDS * 128];
__device__ __align__(16) float g_cnt[N_CLOUDS];

__device__ __forceinline__ int lowerb(const int* __restrict__ a, int n, int v) {
    int lo = 0, hi = n;
    while (lo < hi) { int m = (lo + hi) >> 1; if (a[m] < v) lo = m + 1; else hi = m; }
    return lo;
}

__device__ __forceinline__ float eluf(float v) { return v > 0.f ? v : expm1f(v); }

__device__ __forceinline__ uint32_t s2u(const void* p) {
    return (uint32_t)__cvta_generic_to_shared(p);
}
__device__ __forceinline__ void cpa16(uint32_t d, const void* s) {
    asm volatile("cp.async.cg.shared.global [%0], [%1], 16;" :: "r"(d), "l"(s));
}
#define CP_COMMIT asm volatile("cp.async.commit_group;")
#define CP_WAIT1  asm volatile("cp.async.wait_group 1;")

// ---------------- W_ext^T = [W ; R ; zero-pad]^T -> bf16 [cout][totK] ------
__global__ void concat_wt(const float* __restrict__ W, const float* __restrict__ R,
                          __nv_bfloat16* __restrict__ dst, int wrows, int rrows,
                          int cout, int totK)
{
    int i = blockIdx.x * blockDim.x + threadIdx.x;
    if (i >= totK * cout) return;
    int k = i / cout, c = i - k * cout;
    float v = 0.f;
    if (k < wrows) v = W[k * cout + c];
    else if (k < wrows + rrows) v = R[(k - wrows) * cout + c];
    dst[(size_t)c * totK + k] = __float2bfloat16(v);
}

// ---------------- layer 1 A build (Cin=1): A_ext [n,128] bf16 ----------------
__global__ void __launch_bounds__(128) build_A1(
    const float* __restrict__ pos, const int* __restrict__ src,
    const int* __restrict__ tgt, int nE, float inv2r, __nv_bfloat16* __restrict__ Aout)
{
    __shared__ float A[4][128];
    int warp = threadIdx.x >> 5, lane = threadIdx.x & 31;
    int n = blockIdx.x * 4 + warp;
    float* Aw = A[warp];
    Aw[lane] = 0.f; Aw[lane + 32] = 0.f; Aw[lane + 64] = 0.f; Aw[lane + 96] = 0.f;
    __syncwarp();
    int s0 = lowerb(tgt, nE, n);
    int s1 = lowerb(tgt, nE, n + 1);
    float tx = pos[n * 3 + 0], ty = pos[n * 3 + 1], tz = pos[n * 3 + 2];
    for (int e = s0 + lane; e < s1; e += 32) {
        int sN = src[e];
        float px = fminf(fmaxf((tx - pos[sN * 3 + 0]) * inv2r + 0.5f, 0.f), 1.f) * 4.f;
        float py = fminf(fmaxf((ty - pos[sN * 3 + 1]) * inv2r + 0.5f, 0.f), 1.f) * 4.f;
        float pz = fminf(fmaxf((tz - pos[sN * 3 + 2]) * inv2r + 0.5f, 0.f), 1.f) * 4.f;
        float bx = floorf(px), by = floorf(py), bz = floorf(pz);
        float fx = px - bx, fy = py - by, fz = pz - bz;
        int ix = (int)bx, iy = (int)by, iz = (int)bz;
#pragma unroll
        for (int s = 0; s < 8; s++) {
            int b0 = s & 1, b1 = (s >> 1) & 1, b2 = s >> 2;
            float w = (b0 ? fx : 1.f - fx) * (b1 ? fy : 1.f - fy) * (b2 ? fz : 1.f - fz);
            int wi = min(ix + b0, 4) + 5 * min(iy + b1, 4) + 25 * min(iz + b2, 4);
            atomicAdd(&Aw[wi], w);
        }
    }
    __syncwarp();
    float invd = 1.f / fmaxf((float)(s1 - s0), 1.f);
#pragma unroll
    for (int j = 0; j < 4; j++) {
        int idx = lane + j * 32;
        float out;
        if (idx < 125) out = Aw[idx] * invd;
        else if (idx == 125) out = 1.f;   // root term: x == 1
        else out = 0.f;
        Aout[(size_t)n * 128 + idx] = __float2bfloat16(out);
    }
}

// ---------------- layers 2/3 A build (Cin=64): A_ext [n,8064] bf16 -----------
// max_nb=32 => exactly one 32-edge chunk. Spline params staged once; all xj
// prefetched into registers (MLP=cnt), then fully-unrolled smem accumulation.
__global__ void __launch_bounds__(64) build_A64(
    const float* __restrict__ xin, const float* __restrict__ pos,
    const int* __restrict__ src, const int* __restrict__ tgt, int nE,
    float inv2r, __nv_bfloat16* __restrict__ Aout)
{
    __shared__ float A[8000];          // 125*64
    __shared__ float w_s[32 * 8];
    __shared__ int wi_s[32 * 8];
    __shared__ int esrc[32];
    int n = blockIdx.x;
    int tid = threadIdx.x;  // 64
    float4 z = make_float4(0.f, 0.f, 0.f, 0.f);
    for (int i = tid; i < 2000; i += 64) ((float4*)A)[i] = z;
    int s0 = lowerb(tgt, nE, n);
    int s1 = lowerb(tgt, nE, n + 1);
    int cnt = s1 - s0;                 // <= 32 (max_nb)
    if (tid < 32) esrc[tid] = 0;
    float tx = pos[n * 3 + 0], ty = pos[n * 3 + 1], tz = pos[n * 3 + 2];
    if (tid < cnt) {
        int sN = src[s0 + tid];
        esrc[tid] = sN;
        float px = fminf(fmaxf((tx - pos[sN * 3 + 0]) * inv2r + 0.5f, 0.f), 1.f) * 4.f;
        float py = fminf(fmaxf((ty - pos[sN * 3 + 1]) * inv2r + 0.5f, 0.f), 1.f) * 4.f;
        float pz = fminf(fmaxf((tz - pos[sN * 3 + 2]) * inv2r + 0.5f, 0.f), 1.f) * 4.f;
        float bx = floorf(px), by = floorf(py), bz = floorf(pz);
        float fx = px - bx, fy = py - by, fz = pz - bz;
        int ix = (int)bx, iy = (int)by, iz = (int)bz;
#pragma unroll
        for (int s = 0; s < 8; s++) {
            int b0 = s & 1, b1 = (s >> 1) & 1, b2 = s >> 2;
            float w = (b0 ? fx : 1.f - fx) * (b1 ? fy : 1.f - fy) * (b2 ? fz : 1.f - fz);
            int wi = min(ix + b0, 4) + 5 * min(iy + b1, 4) + 25 * min(iz + b2, 4);
            w_s[tid * 8 + s] = w;
            wi_s[tid * 8 + s] = wi << 6;
        }
    }
    __syncthreads();

    float xj[32];
#pragma unroll
    for (int j = 0; j < 32; j++)
        xj[j] = (j < cnt) ? xin[(size_t)esrc[j] * 64 + tid] : 0.f;

#pragma unroll
    for (int j = 0; j < 32; j++) {
        if (j >= cnt) break;
#pragma unroll
        for (int s = 0; s < 8; s++)
            A[wi_s[j * 8 + s] + tid] += w_s[j * 8 + s] * xj[j];
    }
    __syncthreads();

    float invd = 1.f / fmaxf((float)cnt, 1.f);
    size_t base = (size_t)n * 8064;
    for (int i = tid; i < 2000; i += 64) {
        float4 v = ((float4*)A)[i];
        __nv_bfloat162 p0 = __floats2bfloat162_rn(v.x * invd, v.y * invd);
        __nv_bfloat162 p1 = __floats2bfloat162_rn(v.z * invd, v.w * invd);
        uint2 u;
        u.x = *(uint32_t*)&p0; u.y = *(uint32_t*)&p1;
        *(uint2*)(Aout + base + (size_t)i * 4) = u;
    }
    Aout[base + 8000 + tid] = __float2bfloat16(xin[(size_t)n * 64 + tid]);  // root cols
}

// ---------------- generic row gather ----------------
__global__ void gather_rows(const float* __restrict__ srcv, const int* __restrict__ idx,
                            float* __restrict__ dst, int n, int C)
{
    int i = blockIdx.x * blockDim.x + threadIdx.x;
    if (i >= n * C) return;
    int r = i / C, c = i - r * C;
    dst[i] = srcv[(size_t)idx[r] * C + c];
}

// ---------------- bf16 tensor-core GEMM (+bias+ELU), cp.async 2-stage --------
// C[M,N] = A[M,K] @ Bt[N,K]^T. M%BM==0, N%64==0, K%32==0. 256 thr = 8 warps.
template<int BM, int WARPS_M, int WARPS_N>
__global__ void __launch_bounds__(256) bmma_gemm_elu(
    const __nv_bfloat16* __restrict__ A, const __nv_bfloat16* __restrict__ Bt,
    const float* __restrict__ bias, float* __restrict__ C, int N, int Kd)
{
    constexpr int BN = 64, BK = 32, KS = BK + 8;  // 40-half stride: conflict-free
    constexpr int WM = BM / WARPS_M, WN = BN / WARPS_N;
    constexpr int MT = WM / 16, NT = WN / 8;
    __shared__ __nv_bfloat16 As[2][BM * KS];
    __shared__ __nv_bfloat16 Bs[2][BN * KS];

    int tid = threadIdx.x, warp = tid >> 5, lane = tid & 31;
    int wm = warp % WARPS_M, wn = warp / WARPS_M;
    int m0 = wm * WM, n0 = wn * WN;
    size_t rowBase = (size_t)blockIdx.x * BM;
    int colBase = blockIdx.y * BN;
    int g = lane >> 2, tg = lane & 3;

    float acc[MT][NT][4] = {};

    auto stage = [&](int k0, int buf) {
#pragma unroll
        for (int i = tid; i < BM * 4; i += 256) {
            int r = i >> 2, c = (i & 3) * 8;
            cpa16(s2u(&As[buf][r * KS + c]), A + (rowBase + r) * (size_t)Kd + k0 + c);
        }
#pragma unroll
        for (int i = tid; i < BN * 4; i += 256) {
            int r = i >> 2, c = (i & 3) * 8;
            cpa16(s2u(&Bs[buf][r * KS + c]), Bt + (size_t)(colBase + r) * Kd + k0 + c);
        }
    };

    int nk = Kd / BK;
    stage(0, 0);
    CP_COMMIT;
    for (int it = 0; it < nk; ++it) {
        if (it + 1 < nk) stage((it + 1) * BK, (it + 1) & 1);
        CP_COMMIT;
        CP_WAIT1;
        __syncthreads();
        const __nv_bfloat16* as = As[it & 1];
        const __nv_bfloat16* bs = Bs[it & 1];
#pragma unroll
        for (int ks = 0; ks < 2; ks++) {
            int kk = ks * 16;
            uint32_t af[MT][4], bfr[NT][2];
#pragma unroll
            for (int mt = 0; mt < MT; mt++) {
                int r = m0 + mt * 16 + g;
                const uint32_t* p0 = (const uint32_t*)(as + r * KS + kk + 2 * tg);
                const uint32_t* p1 = (const uint32_t*)(as + (r + 8) * KS + kk + 2 * tg);
                af[mt][0] = p0[0]; af[mt][1] = p1[0];
                af[mt][2] = p0[4]; af[mt][3] = p1[4];
            }
#pragma unroll
            for (int nt = 0; nt < NT; nt++) {
                int c = n0 + nt * 8 + g;
                const uint32_t* q = (const uint32_t*)(bs + c * KS + kk + 2 * tg);
                bfr[nt][0] = q[0]; bfr[nt][1] = q[4];
            }
#pragma unroll
            for (int mt = 0; mt < MT; mt++)
#pragma unroll
                for (int nt = 0; nt < NT; nt++) {
                    asm volatile(
                        "mma.sync.aligned.m16n8k16.row.col.f32.bf16.bf16.f32 "
                        "{%0,%1,%2,%3}, {%4,%5,%6,%7}, {%8,%9}, {%0,%1,%2,%3};"
                        : "+f"(acc[mt][nt][0]), "+f"(acc[mt][nt][1]),
                          "+f"(acc[mt][nt][2]), "+f"(acc[mt][nt][3])
                        : "r"(af[mt][0]), "r"(af[mt][1]), "r"(af[mt][2]), "r"(af[mt][3]),
                          "r"(bfr[nt][0]), "r"(bfr[nt][1]));
                }
        }
        __syncthreads();
    }

    // --- epilogue: bias + ELU, coalesced float2 stores ---
#pragma unroll
    for (int mt = 0; mt < MT; mt++) {
        size_t r0 = rowBase + m0 + mt * 16 + g;
#pragma unroll
        for (int nt = 0; nt < NT; nt++) {
            int c = colBase + n0 + nt * 8 + (tg << 1);
            float b0v = bias[c], b1v = bias[c + 1];
            float2 o0 = make_float2(eluf(acc[mt][nt][0] + b0v), eluf(acc[mt][nt][1] + b1v));
            float2 o1 = make_float2(eluf(acc[mt][nt][2] + b0v), eluf(acc[mt][nt][3] + b1v));
            *(float2*)(C + r0 * N + c) = o0;
            *(float2*)(C + (r0 + 8) * N + c) = o1;
        }
    }
}

// ---------------- pooling ----------------
__global__ void zero_pool(float* __restrict__ sums, float* __restrict__ cnt)
{
    int i = blockIdx.x * blockDim.x + threadIdx.x;
    if (i < N_CLOUDS * 128) sums[i] = 0.f;
    if (i < N_CLOUDS) cnt[i] = 0.f;
}

__global__ void pool_kernel(const float* __restrict__ x3, const int* __restrict__ batch,
                            const int* __restrict__ idx1, const int* __restrict__ idx2,
                            int n3, float* __restrict__ sums, float* __restrict__ cnt)
{
    int i = blockIdx.x * blockDim.x + threadIdx.x;
    if (i >= n3 * 128) return;
    int j = i >> 7, c = i & 127;
    int b = batch[idx1[idx2[j]]];
    atomicAdd(&sums[b * 128 + c], x3[i]);
    if (c == 0) atomicAdd(&cnt[b], 1.f);
}

// ---------------- MLP head + log_softmax, one block per cloud ----------------
__global__ void head_kernel(const float* __restrict__ sums, const float* __restrict__ cnt,
                            const float* __restrict__ lw1, const float* __restrict__ lb1,
                            const float* __restrict__ lw2, const float* __restrict__ lb2,
                            const float* __restrict__ lw3, const float* __restrict__ lb3,
                            float* __restrict__ out)
{
    __shared__ float g[128], h1[256], h2[256], lg[10];
    int b = blockIdx.x, tid = threadIdx.x;  // 256 threads
    if (tid < 128) g[tid] = sums[b * 128 + tid] / fmaxf(cnt[b], 1.f);
    __syncthreads();
    float a = lb1[tid];
    for (int c = 0; c < 128; c++) a += g[c] * lw1[c * 256 + tid];
    h1[tid] = eluf(a);
    __syncthreads();
    a = lb2[tid];
    for (int c = 0; c < 256; c++) a += h1[c] * lw2[c * 256 + tid];
    h2[tid] = eluf(a);
    __syncthreads();
    if (tid < 10) {
        a = lb3[tid];
        for (int c = 0; c < 256; c++) a += h2[c] * lw3[c * 10 + tid];
        lg[tid] = a;
    }
    __syncthreads();
    if (tid == 0) {
        float m = lg[0];
        for (int k = 1; k < 10; k++) m = fmaxf(m, lg[k]);
        float s = 0.f;
        for (int k = 0; k < 10; k++) s += expf(lg[k] - m);
        float ls = logf(s);
        for (int k = 0; k < 10; k++) out[b * 10 + k] = lg[k] - m - ls;
    }
}

// ---------------- host driver (graph-capturable: kernel launches only) -------
extern "C" void kernel_launch(void* const* d_in, const int* in_sizes, int n_in,
                              void* d_out, int out_size)
{
    const float* pos = (const float*)d_in[0];
    const int* batch = (const int*)d_in[1];
    const int* src1 = (const int*)d_in[2];
    const int* tgt1 = (const int*)d_in[3];
    const int* src2 = (const int*)d_in[4];
    const int* tgt2 = (const int*)d_in[5];
    const int* src3 = (const int*)d_in[6];
    const int* tgt3 = (const int*)d_in[7];
    const int* idx1 = (const int*)d_in[8];
    const int* idx2 = (const int*)d_in[9];
    const float* W1 = (const float*)d_in[10];
    const float* R1 = (const float*)d_in[11];
    const float* b1 = (const float*)d_in[12];
    const float* W2 = (const float*)d_in[13];
    const float* R2 = (const float*)d_in[14];
    const float* b2 = (const float*)d_in[15];
    const float* W3 = (const float*)d_in[16];
    const float* R3 = (const float*)d_in[17];
    const float* b3 = (const float*)d_in[18];
    const float* lw1 = (const float*)d_in[19];
    const float* lb1 = (const float*)d_in[20];
    const float* lw2 = (const float*)d_in[21];
    const float* lb2 = (const float*)d_in[22];
    const float* lw3 = (const float*)d_in[23];
    const float* lb3 = (const float*)d_in[24];
    float* out = (float*)d_out;

    int n1 = in_sizes[0] / 3;
    int E1 = in_sizes[2], E2 = in_sizes[4], E3 = in_sizes[6];
    int n2 = in_sizes[8], n3 = in_sizes[9];

    __nv_bfloat16 *pA, *pw1, *pw2, *pw3;
    float *px1, *px2in, *px2out, *px3in, *px3out, *ppos2, *ppos3, *ppool, *pcnt;
    cudaGetSymbolAddress((void**)&pA, g_A);
    cudaGetSymbolAddress((void**)&px1, g_x1);
    cudaGetSymbolAddress((void**)&px2in, g_x2in);
    cudaGetSymbolAddress((void**)&px2out, g_x2out);
    cudaGetSymbolAddress((void**)&px3in, g_x3in);
    cudaGetSymbolAddress((void**)&px3out, g_x3out);
    cudaGetSymbolAddress((void**)&ppos2, g_pos2);
    cudaGetSymbolAddress((void**)&ppos3, g_pos3);
    cudaGetSymbolAddress((void**)&pw1, g_w1e);
    cudaGetSymbolAddress((void**)&pw2, g_w2e);
    cudaGetSymbolAddress((void**)&pw3, g_w3e);
    cudaGetSymbolAddress((void**)&ppool, g_pool);
    cudaGetSymbolAddress((void**)&pcnt, g_cnt);

    // transposed bf16 weight concat (Wt = [W ; R ; pad]^T, [cout][totK])
    concat_wt<<<(128 * 64 + 255) / 256, 256>>>(W1, R1, pw1, 125, 1, 64, 128);
    concat_wt<<<(8064 * 64 + 255) / 256, 256>>>(W2, R2, pw2, 8000, 64, 64, 8064);
    concat_wt<<<(8064 * 128 + 255) / 256, 256>>>(W3, R3, pw3, 8000, 64, 128, 8064);

    // ---- layer 1 (n1=32768, Cin=1, Cout=64, r=0.2) ----
    build_A1<<<n1 / 4, 128>>>(pos, src1, tgt1, E1, 1.f / 0.4f, pA);
    bmma_gemm_elu<128, 4, 2><<<dim3(n1 / 128, 1), 256>>>(pA, pw1, b1, px1, 64, 128);

    // ---- layer 2 (n2=16384, Cin=64, Cout=64, r=0.4) ----
    gather_rows<<<(n2 * 64 + 255) / 256, 256>>>(px1, idx1, px2in, n2, 64);
    gather_rows<<<(n2 * 3 + 255) / 256, 256>>>(pos, idx1, ppos2, n2, 3);
    build_A64<<<n2, 64>>>(px2in, ppos2, src2, tgt2, E2, 1.f / 0.8f, pA);
    bmma_gemm_elu<64, 2, 4><<<dim3(n2 / 64, 1), 256>>>(pA, pw2, b2, px2out, 64, 8064);

    // ---- layer 3 (n3=4096, Cin=64, Cout=128, r=1.0) ----
    gather_rows<<<(n3 * 64 + 255) / 256, 256>>>(px2out, idx2, px3in, n3, 64);
    gather_rows<<<(n3 * 3 + 255) / 256, 256>>>(ppos2, idx2, ppos3, n3, 3);
    build_A64<<<n3, 64>>>(px3in, ppos3, src3, tgt3, E3, 1.f / 2.0f, pA);
    bmma_gemm_elu<64, 2, 4><<<dim3(n3 / 64, 2), 256>>>(pA, pw3, b3, px3out, 128, 8064);

    // ---- pool + head ----
    zero_pool<<<8, 256>>>(ppool, pcnt);
    pool_kernel<<<(n3 * 128 + 255) / 256, 256>>>(px3out, batch, idx1, idx2, n3, ppool, pcnt);
    head_kernel<<<N_CLOUDS, 256>>>(ppool, pcnt, lw1, lb1, lw2, lb2, lw3, lb3, out);
}

// round 9
// speedup vs baseline: 3.6756x; 1.1965x over previous
#include <cuda_runtime.h>
#include <cuda_bf16.h>
#include <math.h>
#include <stdint.h>

#define N_CLOUDS 16

// ---------------- static scratch (no allocations allowed) ----------------
__device__ __align__(16) __nv_bfloat16 g_A[(size_t)16384 * 8064];  // reused by all layers
__device__ __align__(16) float g_x1[32768 * 64];
__device__ __align__(16) float g_x2in[16384 * 64];
__device__ __align__(16) float g_x2out[16384 * 64];
__device__ __align__(16) float g_x3in[4096 * 64];
__device__ __align__(16) float g_x3out[4096 * 128];
__device__ __align__(16) float g_pos2[16384 * 3];
__device__ __align__(16) float g_pos3[4096 * 3];
__device__ __align__(16) __nv_bfloat16 g_w1e[64 * 128];    // transposed [N][K]
__device__ __align__(16) __nv_bfloat16 g_w2e[64 * 8064];   // transposed [N][K]
__device__ __align__(16) __nv_bfloat16 g_w3e[128 * 8064];  // transposed [N][K]
__device__ __align__(16) float g_pool[N_CLOUDS * 128];
__device__ __align__(16) float g_cnt[N_CLOUDS];

__device__ __forceinline__ int lowerb(const int* __restrict__ a, int n, int v) {
    int lo = 0, hi = n;
    while (lo < hi) { int m = (lo + hi) >> 1; if (a[m] < v) lo = m + 1; else hi = m; }
    return lo;
}

__device__ __forceinline__ float eluf(float v) { return v > 0.f ? v : expm1f(v); }

__device__ __forceinline__ uint32_t s2u(const void* p) {
    return (uint32_t)__cvta_generic_to_shared(p);
}
__device__ __forceinline__ void cpa16(uint32_t d, const void* s) {
    asm volatile("cp.async.cg.shared.global [%0], [%1], 16;" :: "r"(d), "l"(s));
}
#define CP_COMMIT asm volatile("cp.async.commit_group;")
#define CP_WAIT1  asm volatile("cp.async.wait_group 1;")

// ---------------- W_ext^T = [W ; R ; zero-pad]^T -> bf16 [cout][totK] ------
__global__ void concat_wt(const float* __restrict__ W, const float* __restrict__ R,
                          __nv_bfloat16* __restrict__ dst, int wrows, int rrows,
                          int cout, int totK)
{
    int i = blockIdx.x * blockDim.x + threadIdx.x;
    if (i >= totK * cout) return;
    int k = i / cout, c = i - k * cout;
    float v = 0.f;
    if (k < wrows) v = W[k * cout + c];
    else if (k < wrows + rrows) v = R[(k - wrows) * cout + c];
    dst[(size_t)c * totK + k] = __float2bfloat16(v);
}

// ---------------- layer 1 A build (Cin=1): A_ext [n,128] bf16 ----------------
__global__ void __launch_bounds__(128) build_A1(
    const float* __restrict__ pos, const int* __restrict__ src,
    const int* __restrict__ tgt, int nE, float inv2r, __nv_bfloat16* __restrict__ Aout)
{
    __shared__ float A[4][128];
    int warp = threadIdx.x >> 5, lane = threadIdx.x & 31;
    int n = blockIdx.x * 4 + warp;
    float* Aw = A[warp];
    Aw[lane] = 0.f; Aw[lane + 32] = 0.f; Aw[lane + 64] = 0.f; Aw[lane + 96] = 0.f;
    __syncwarp();
    int s0 = lowerb(tgt, nE, n);
    int s1 = lowerb(tgt, nE, n + 1);
    float tx = pos[n * 3 + 0], ty = pos[n * 3 + 1], tz = pos[n * 3 + 2];
    for (int e = s0 + lane; e < s1; e += 32) {
        int sN = src[e];
        float px = fminf(fmaxf((tx - pos[sN * 3 + 0]) * inv2r + 0.5f, 0.f), 1.f) * 4.f;
        float py = fminf(fmaxf((ty - pos[sN * 3 + 1]) * inv2r + 0.5f, 0.f), 1.f) * 4.f;
        float pz = fminf(fmaxf((tz - pos[sN * 3 + 2]) * inv2r + 0.5f, 0.f), 1.f) * 4.f;
        float bx = floorf(px), by = floorf(py), bz = floorf(pz);
        float fx = px - bx, fy = py - by, fz = pz - bz;
        int ix = (int)bx, iy = (int)by, iz = (int)bz;
#pragma unroll
        for (int s = 0; s < 8; s++) {
            int b0 = s & 1, b1 = (s >> 1) & 1, b2 = s >> 2;
            float w = (b0 ? fx : 1.f - fx) * (b1 ? fy : 1.f - fy) * (b2 ? fz : 1.f - fz);
            int wi = min(ix + b0, 4) + 5 * min(iy + b1, 4) + 25 * min(iz + b2, 4);
            atomicAdd(&Aw[wi], w);
        }
    }
    __syncwarp();
    float invd = 1.f / fmaxf((float)(s1 - s0), 1.f);
#pragma unroll
    for (int j = 0; j < 4; j++) {
        int idx = lane + j * 32;
        float out;
        if (idx < 125) out = Aw[idx] * invd;
        else if (idx == 125) out = 1.f;   // root term: x == 1
        else out = 0.f;
        Aout[(size_t)n * 128 + idx] = __float2bfloat16(out);
    }
}

// ---------------- layers 2/3 A build (Cin=64): A_ext [n,8064] bf16 -----------
// Bucket-sorted edge-corners (125 buckets), register accumulator per (k,c):
// ~13KB smem (vs 35KB dense) -> 3x occupancy, no dense zero/readback.
__global__ void __launch_bounds__(64) build_A64(
    const float* __restrict__ xin, const float* __restrict__ pos,
    const int* __restrict__ src, const int* __restrict__ tgt, int nE,
    float inv2r, __nv_bfloat16* __restrict__ Aout)
{
    __shared__ float xj_s[32 * 64];        // 8KB
    __shared__ float tw[256];
    __shared__ int twi[256];
    __shared__ float w_sorted[256];
    __shared__ unsigned char j_sorted[256];
    __shared__ int cnts[125];
    __shared__ int bstart[126];
    __shared__ int cursor[125];
    __shared__ int esrc_s[32];

    int n = blockIdx.x, tid = threadIdx.x;   // 64 threads, tid = channel
    for (int i = tid; i < 125; i += 64) cnts[i] = 0;
    int s0 = lowerb(tgt, nE, n);
    int s1 = lowerb(tgt, nE, n + 1);
    int cnt = min(s1 - s0, 32);              // max_nb = 32
    float invd = 1.f / fmaxf((float)cnt, 1.f);
    float tx = pos[n * 3 + 0], ty = pos[n * 3 + 1], tz = pos[n * 3 + 2];
    __syncthreads();
    if (tid < cnt) {
        int sN = src[s0 + tid];
        esrc_s[tid] = sN;
        float px = fminf(fmaxf((tx - pos[sN * 3 + 0]) * inv2r + 0.5f, 0.f), 1.f) * 4.f;
        float py = fminf(fmaxf((ty - pos[sN * 3 + 1]) * inv2r + 0.5f, 0.f), 1.f) * 4.f;
        float pz = fminf(fmaxf((tz - pos[sN * 3 + 2]) * inv2r + 0.5f, 0.f), 1.f) * 4.f;
        float bx = floorf(px), by = floorf(py), bz = floorf(pz);
        float fx = px - bx, fy = py - by, fz = pz - bz;
        int ix = (int)bx, iy = (int)by, iz = (int)bz;
#pragma unroll
        for (int s = 0; s < 8; s++) {
            int b0 = s & 1, b1 = (s >> 1) & 1, b2 = s >> 2;
            float w = (b0 ? fx : 1.f - fx) * (b1 ? fy : 1.f - fy) * (b2 ? fz : 1.f - fz);
            int wi = min(ix + b0, 4) + 5 * min(iy + b1, 4) + 25 * min(iz + b2, 4);
            tw[tid * 8 + s] = w * invd;       // fold degree normalization here
            twi[tid * 8 + s] = wi;
            atomicAdd(&cnts[wi], 1);
        }
    }
    __syncthreads();
    if (tid == 0) {
        int s = 0;
#pragma unroll 5
        for (int k = 0; k < 125; k++) { bstart[k] = s; s += cnts[k]; }
        bstart[125] = s;
    }
    __syncthreads();
    for (int i = tid; i < 125; i += 64) cursor[i] = bstart[i];
    __syncthreads();
    if (tid < cnt) {
#pragma unroll
        for (int s = 0; s < 8; s++) {
            int wi = twi[tid * 8 + s];
            int p = atomicAdd(&cursor[wi], 1);
            w_sorted[p] = tw[tid * 8 + s];
            j_sorted[p] = (unsigned char)tid;
        }
    }
    // stage xj (all 64 threads)
    for (int j = 0; j < cnt; j++)
        xj_s[j * 64 + tid] = xin[(size_t)esrc_s[j] * 64 + tid];
    __syncthreads();

    size_t base = (size_t)n * 8064;
    for (int k = 0; k < 125; k++) {
        float acc = 0.f;
        int e0 = bstart[k], e1 = bstart[k + 1];
        for (int i = e0; i < e1; i++)
            acc += w_sorted[i] * xj_s[(int)j_sorted[i] * 64 + tid];
        Aout[base + k * 64 + tid] = __float2bfloat16(acc);
    }
    Aout[base + 8000 + tid] = __float2bfloat16(xin[(size_t)n * 64 + tid]);  // root cols
}

// ---------------- generic row gather ----------------
__global__ void gather_rows(const float* __restrict__ srcv, const int* __restrict__ idx,
                            float* __restrict__ dst, int n, int C)
{
    int i = blockIdx.x * blockDim.x + threadIdx.x;
    if (i >= n * C) return;
    int r = i / C, c = i - r * C;
    dst[i] = srcv[(size_t)idx[r] * C + c];
}

// ---------------- bf16 mma GEMM (+bias+ELU), 3-stage cp.async, BK=64 ---------
// C[M,N] = A[M,K] @ Bt[N,K]^T. M%64==0, N%64==0, K%64==0. 256 thr = 8 warps.
// Dynamic smem: 3 * (64+64) * 72 halfs = 55296 B.
template<int WARPS_M, int WARPS_N>
__global__ void __launch_bounds__(256) bmma_gemm_elu(
    const __nv_bfloat16* __restrict__ A, const __nv_bfloat16* __restrict__ Bt,
    const float* __restrict__ bias, float* __restrict__ C, int N, int Kd)
{
    constexpr int BM = 64, BN = 64, BK = 64, KS = BK + 8;  // 72-half stride
    constexpr int WM = BM / WARPS_M, WN = BN / WARPS_N;
    constexpr int MT = WM / 16, NT = WN / 8;
    extern __shared__ __nv_bfloat16 smem[];
    __nv_bfloat16* As = smem;                      // [3][BM*KS]
    __nv_bfloat16* Bs = smem + 3 * BM * KS;        // [3][BN*KS]

    int tid = threadIdx.x, warp = tid >> 5, lane = tid & 31;
    int wm = warp % WARPS_M, wn = warp / WARPS_M;
    int m0 = wm * WM, n0 = wn * WN;
    size_t rowBase = (size_t)blockIdx.x * BM;
    int colBase = blockIdx.y * BN;
    int g = lane >> 2, tg = lane & 3;

    float acc[MT][NT][4] = {};

    auto stage = [&](int k0, int buf) {
        __nv_bfloat16* as = As + buf * BM * KS;
        __nv_bfloat16* bs = Bs + buf * BN * KS;
#pragma unroll
        for (int i = tid; i < BM * 8; i += 256) {
            int r = i >> 3, c = (i & 7) * 8;
            cpa16(s2u(as + r * KS + c), A + (rowBase + r) * (size_t)Kd + k0 + c);
        }
#pragma unroll
        for (int i = tid; i < BN * 8; i += 256) {
            int r = i >> 3, c = (i & 7) * 8;
            cpa16(s2u(bs + r * KS + c), Bt + (size_t)(colBase + r) * Kd + k0 + c);
        }
    };

    int nk = Kd / BK;
    stage(0, 0);
    CP_COMMIT;
    if (nk > 1) stage(BK, 1);
    CP_COMMIT;

    for (int it = 0; it < nk; ++it) {
        CP_WAIT1;               // group 'it' complete
        __syncthreads();        // also guards buffer (it+2)%3 reuse below
        if (it + 2 < nk) stage((it + 2) * BK, (it + 2) % 3);
        CP_COMMIT;              // always commit (empty group keeps counts aligned)
        const __nv_bfloat16* as = As + (it % 3) * BM * KS;
        const __nv_bfloat16* bs = Bs + (it % 3) * BN * KS;
#pragma unroll
        for (int ks = 0; ks < 4; ks++) {
            int kk = ks * 16;
            uint32_t af[MT][4], bfr[NT][2];
#pragma unroll
            for (int mt = 0; mt < MT; mt++) {
                int r = m0 + mt * 16 + g;
                const uint32_t* p0 = (const uint32_t*)(as + r * KS + kk + 2 * tg);
                const uint32_t* p1 = (const uint32_t*)(as + (r + 8) * KS + kk + 2 * tg);
                af[mt][0] = p0[0]; af[mt][1] = p1[0];
                af[mt][2] = p0[4]; af[mt][3] = p1[4];
            }
#pragma unroll
            for (int nt = 0; nt < NT; nt++) {
                int c = n0 + nt * 8 + g;
                const uint32_t* q = (const uint32_t*)(bs + c * KS + kk + 2 * tg);
                bfr[nt][0] = q[0]; bfr[nt][1] = q[4];
            }
#pragma unroll
            for (int mt = 0; mt < MT; mt++)
#pragma unroll
                for (int nt = 0; nt < NT; nt++) {
                    asm volatile(
                        "mma.sync.aligned.m16n8k16.row.col.f32.bf16.bf16.f32 "
                        "{%0,%1,%2,%3}, {%4,%5,%6,%7}, {%8,%9}, {%0,%1,%2,%3};"
                        : "+f"(acc[mt][nt][0]), "+f"(acc[mt][nt][1]),
                          "+f"(acc[mt][nt][2]), "+f"(acc[mt][nt][3])
                        : "r"(af[mt][0]), "r"(af[mt][1]), "r"(af[mt][2]), "r"(af[mt][3]),
                          "r"(bfr[nt][0]), "r"(bfr[nt][1]));
                }
        }
    }

    // --- epilogue: bias + ELU, coalesced float2 stores ---
#pragma unroll
    for (int mt = 0; mt < MT; mt++) {
        size_t r0 = rowBase + m0 + mt * 16 + g;
#pragma unroll
        for (int nt = 0; nt < NT; nt++) {
            int c = colBase + n0 + nt * 8 + (tg << 1);
            float b0v = bias[c], b1v = bias[c + 1];
            float2 o0 = make_float2(eluf(acc[mt][nt][0] + b0v), eluf(acc[mt][nt][1] + b1v));
            float2 o1 = make_float2(eluf(acc[mt][nt][2] + b0v), eluf(acc[mt][nt][3] + b1v));
            *(float2*)(C + r0 * N + c) = o0;
            *(float2*)(C + (r0 + 8) * N + c) = o1;
        }
    }
}

// ---------------- pooling ----------------
__global__ void zero_pool(float* __restrict__ sums, float* __restrict__ cnt)
{
    int i = blockIdx.x * blockDim.x + threadIdx.x;
    if (i < N_CLOUDS * 128) sums[i] = 0.f;
    if (i < N_CLOUDS) cnt[i] = 0.f;
}

__global__ void pool_kernel(const float* __restrict__ x3, const int* __restrict__ batch,
                            const int* __restrict__ idx1, const int* __restrict__ idx2,
                            int n3, float* __restrict__ sums, float* __restrict__ cnt)
{
    int i = blockIdx.x * blockDim.x + threadIdx.x;
    if (i >= n3 * 128) return;
    int j = i >> 7, c = i & 127;
    int b = batch[idx1[idx2[j]]];
    atomicAdd(&sums[b * 128 + c], x3[i]);
    if (c == 0) atomicAdd(&cnt[b], 1.f);
}

// ---------------- MLP head + log_softmax, one block per cloud ----------------
__global__ void head_kernel(const float* __restrict__ sums, const float* __restrict__ cnt,
                            const float* __restrict__ lw1, const float* __restrict__ lb1,
                            const float* __restrict__ lw2, const float* __restrict__ lb2,
                            const float* __restrict__ lw3, const float* __restrict__ lb3,
                            float* __restrict__ out)
{
    __shared__ float g[128], h1[256], h2[256], lg[10];
    int b = blockIdx.x, tid = threadIdx.x;  // 256 threads
    if (tid < 128) g[tid] = sums[b * 128 + tid] / fmaxf(cnt[b], 1.f);
    __syncthreads();
    float a = lb1[tid];
    for (int c = 0; c < 128; c++) a += g[c] * lw1[c * 256 + tid];
    h1[tid] = eluf(a);
    __syncthreads();
    a = lb2[tid];
    for (int c = 0; c < 256; c++) a += h1[c] * lw2[c * 256 + tid];
    h2[tid] = eluf(a);
    __syncthreads();
    if (tid < 10) {
        a = lb3[tid];
        for (int c = 0; c < 256; c++) a += h2[c] * lw3[c * 10 + tid];
        lg[tid] = a;
    }
    __syncthreads();
    if (tid == 0) {
        float m = lg[0];
        for (int k = 1; k < 10; k++) m = fmaxf(m, lg[k]);
        float s = 0.f;
        for (int k = 0; k < 10; k++) s += expf(lg[k] - m);
        float ls = logf(s);
        for (int k = 0; k < 10; k++) out[b * 10 + k] = lg[k] - m - ls;
    }
}

// ---------------- host driver (graph-capturable: kernel launches only) -------
extern "C" void kernel_launch(void* const* d_in, const int* in_sizes, int n_in,
                              void* d_out, int out_size)
{
    const float* pos = (const float*)d_in[0];
    const int* batch = (const int*)d_in[1];
    const int* src1 = (const int*)d_in[2];
    const int* tgt1 = (const int*)d_in[3];
    const int* src2 = (const int*)d_in[4];
    const int* tgt2 = (const int*)d_in[5];
    const int* src3 = (const int*)d_in[6];
    const int* tgt3 = (const int*)d_in[7];
    const int* idx1 = (const int*)d_in[8];
    const int* idx2 = (const int*)d_in[9];
    const float* W1 = (const float*)d_in[10];
    const float* R1 = (const float*)d_in[11];
    const float* b1 = (const float*)d_in[12];
    const float* W2 = (const float*)d_in[13];
    const float* R2 = (const float*)d_in[14];
    const float* b2 = (const float*)d_in[15];
    const float* W3 = (const float*)d_in[16];
    const float* R3 = (const float*)d_in[17];
    const float* b3 = (const float*)d_in[18];
    const float* lw1 = (const float*)d_in[19];
    const float* lb1 = (const float*)d_in[20];
    const float* lw2 = (const float*)d_in[21];
    const float* lb2 = (const float*)d_in[22];
    const float* lw3 = (const float*)d_in[23];
    const float* lb3 = (const float*)d_in[24];
    float* out = (float*)d_out;

    int n1 = in_sizes[0] / 3;
    int E1 = in_sizes[2], E2 = in_sizes[4], E3 = in_sizes[6];
    int n2 = in_sizes[8], n3 = in_sizes[9];

    __nv_bfloat16 *pA, *pw1, *pw2, *pw3;
    float *px1, *px2in, *px2out, *px3in, *px3out, *ppos2, *ppos3, *ppool, *pcnt;
    cudaGetSymbolAddress((void**)&pA, g_A);
    cudaGetSymbolAddress((void**)&px1, g_x1);
    cudaGetSymbolAddress((void**)&px2in, g_x2in);
    cudaGetSymbolAddress((void**)&px2out, g_x2out);
    cudaGetSymbolAddress((void**)&px3in, g_x3in);
    cudaGetSymbolAddress((void**)&px3out, g_x3out);
    cudaGetSymbolAddress((void**)&ppos2, g_pos2);
    cudaGetSymbolAddress((void**)&ppos3, g_pos3);
    cudaGetSymbolAddress((void**)&pw1, g_w1e);
    cudaGetSymbolAddress((void**)&pw2, g_w2e);
    cudaGetSymbolAddress((void**)&pw3, g_w3e);
    cudaGetSymbolAddress((void**)&ppool, g_pool);
    cudaGetSymbolAddress((void**)&pcnt, g_cnt);

    const int SMEM_GEMM = 3 * (64 + 64) * 72 * 2;  // 55296 B
    cudaFuncSetAttribute(bmma_gemm_elu<2, 4>,
                         cudaFuncAttributeMaxDynamicSharedMemorySize, SMEM_GEMM);

    // transposed bf16 weight concat (Wt = [W ; R ; pad]^T, [cout][totK])
    concat_wt<<<(128 * 64 + 255) / 256, 256>>>(W1, R1, pw1, 125, 1, 64, 128);
    concat_wt<<<(8064 * 64 + 255) / 256, 256>>>(W2, R2, pw2, 8000, 64, 64, 8064);
    concat_wt<<<(8064 * 128 + 255) / 256, 256>>>(W3, R3, pw3, 8000, 64, 128, 8064);

    // ---- layer 1 (n1=32768, Cin=1, Cout=64, r=0.2) ----
    build_A1<<<n1 / 4, 128>>>(pos, src1, tgt1, E1, 1.f / 0.4f, pA);
    bmma_gemm_elu<2, 4><<<dim3(n1 / 64, 1), 256, SMEM_GEMM>>>(pA, pw1, b1, px1, 64, 128);

    // ---- layer 2 (n2=16384, Cin=64, Cout=64, r=0.4) ----
    gather_rows<<<(n2 * 64 + 255) / 256, 256>>>(px1, idx1, px2in, n2, 64);
    gather_rows<<<(n2 * 3 + 255) / 256, 256>>>(pos, idx1, ppos2, n2, 3);
    build_A64<<<n2, 64>>>(px2in, ppos2, src2, tgt2, E2, 1.f / 0.8f, pA);
    bmma_gemm_elu<2, 4><<<dim3(n2 / 64, 1), 256, SMEM_GEMM>>>(pA, pw2, b2, px2out, 64, 8064);

    // ---- layer 3 (n3=4096, Cin=64, Cout=128, r=1.0) ----
    gather_rows<<<(n3 * 64 + 255) / 256, 256>>>(px2out, idx2, px3in, n3, 64);
    gather_rows<<<(n3 * 3 + 255) / 256, 256>>>(ppos2, idx2, ppos3, n3, 3);
    build_A64<<<n3, 64>>>(px3in, ppos3, src3, tgt3, E3, 1.f / 2.0f, pA);
    bmma_gemm_elu<2, 4><<<dim3(n3 / 64, 2), 256, SMEM_GEMM>>>(pA, pw3, b3, px3out, 128, 8064);

    // ---- pool + head ----
    zero_pool<<<8, 256>>>(ppool, pcnt);
    pool_kernel<<<(n3 * 128 + 255) / 256, 256>>>(px3out, batch, idx1, idx2, n3, ppool, pcnt);
    head_kernel<<<N_CLOUDS, 256>>>(ppool, pcnt, lw1, lb1, lw2, lb2, lw3, lb3, out);
}